// round 6
// baseline (speedup 1.0000x reference)
#include <cuda_runtime.h>
#include <math.h>
#include <stdint.h>

#define NROW      4096
#define NT        512
#define RPT       8
#define NCELL     5
#define POWK      20      // power-iteration steps for outlier eigenvector
#define NEUM      12      // Neumann/Richardson steps per pass (0.41^12 ~ 2e-5)
#define MAX_OUTER 8

// smem: xd[4097] dbl, scrd[96] dbl, rfA[4097] f, rfB[4097] f, scrf[32] f
#define SM_BYTES ((4097 + 96) * 8 + (4097 + 4097 + 32) * 4)

__device__ double g_IM[75];
__device__ int    g_cnt = 0;

__device__ __forceinline__ double warp_red_d(double v) {
#pragma unroll
    for (int o = 16; o; o >>= 1) v += __shfl_down_sync(0xFFFFFFFFu, v, o);
    return v;
}
__device__ __forceinline__ double blk_red_d(double v, double* scr, int tid) {
    int lane = tid & 31, wid = tid >> 5;
    v = warp_red_d(v);
    if (lane == 0) scr[wid] = v;
    __syncthreads();
    if (wid == 0) {
        double u = (lane < 16) ? scr[lane] : 0.0;
#pragma unroll
        for (int o = 8; o; o >>= 1) u += __shfl_down_sync(0xFFFFFFFFu, u, o);
        if (lane == 0) scr[32] = u;
    }
    __syncthreads();
    return scr[32];
}
// 5-way fused fp64 block reduction (2 barriers total)
__device__ __forceinline__ void bredd5(double v[5], double* scr, int tid) {
    int lane = tid & 31, wid = tid >> 5;
#pragma unroll
    for (int k = 0; k < 5; k++) v[k] = warp_red_d(v[k]);
    if (lane == 0) {
#pragma unroll
        for (int k = 0; k < 5; k++) scr[k * 16 + wid] = v[k];
    }
    __syncthreads();
    if (wid < 5) {
        double u = (lane < 16) ? scr[wid * 16 + lane] : 0.0;
#pragma unroll
        for (int o = 8; o; o >>= 1) u += __shfl_down_sync(0xFFFFFFFFu, u, o);
        if (lane == 0) scr[80 + wid] = u;
    }
    __syncthreads();
#pragma unroll
    for (int k = 0; k < 5; k++) v[k] = scr[80 + k];
}
// single-barrier fp32 block reduction
__device__ __forceinline__ float bred1(float v, float* scr, int tid) {
    const int lane = tid & 31, wid = tid >> 5;
#pragma unroll
    for (int o = 16; o; o >>= 1) v += __shfl_xor_sync(0xFFFFFFFFu, v, o);
    if (lane == 0) scr[wid] = v;
    __syncthreads();
    float u = scr[lane & 15];
#pragma unroll
    for (int o = 8; o; o >>= 1) u += __shfl_xor_sync(0xFFFFFFFFu, u, o);
    return u;
}

#define GATHF(arr, q0, q1, q2)                                                \
    ( *(const float*)((const char*)(arr) + ((q0) & 0xFFFFu))                  \
    + *(const float*)((const char*)(arr) + ((q0) >> 16))                      \
    + *(const float*)((const char*)(arr) + ((q1) & 0xFFFFu))                  \
    + *(const float*)((const char*)(arr) + ((q1) >> 16))                      \
    + *(const float*)((const char*)(arr) + ((q2) & 0xFFFFu))                  \
    + *(const float*)((const char*)(arr) + ((q2) >> 16)) )
#define GATHD(arr, q0, q1, q2)                                                \
    ( *(const double*)((const char*)(arr) + (((q0) & 0xFFFFu) << 1))          \
    + *(const double*)((const char*)(arr) + (((q0) >> 16)     << 1))          \
    + *(const double*)((const char*)(arr) + (((q1) & 0xFFFFu) << 1))          \
    + *(const double*)((const char*)(arr) + (((q1) >> 16)     << 1))          \
    + *(const double*)((const char*)(arr) + (((q2) & 0xFFFFu) << 1))          \
    + *(const double*)((const char*)(arr) + (((q2) >> 16)     << 1)) )

__global__ __launch_bounds__(NT, 1)
void solve_kernel(const float* __restrict__ th1,
                  const float* __restrict__ th2,
                  const float* __restrict__ th3,
                  const float* __restrict__ cd,
                  const float* __restrict__ Iexp,
                  const int*   __restrict__ nbr,
                  float*       __restrict__ out)
{
    extern __shared__ double sm[];
    double* xd   = sm;               // 4097 (pad slot 4096 == 0)
    double* scrd = sm + 4097;        // 96
    float*  fb   = (float*)(sm + 4193);
    float* rfA  = fb;                // 4097 (pad 0)
    float* rfB  = fb + 4097;         // 4097 (pad 0)
    float* scrf = fb + 8194;         // 32
    __shared__ int s_last;

    const int tid = threadIdx.x;
    const int sys = blockIdx.x;
    const float* th = (sys == 0) ? th1 : ((sys == 1) ? th2 : th3);

    const double L_C     = 8.45e-05;
    const double L_RATIO = 1.0 / sqrt(3.0);
    const double AREA    = sqrt(3.0) * 0.5 * L_C * L_C;
    const double A_SCALE = 1.0e11;
    const double B_SCALE = 1.0e23;

    const double D   = (double)th[0];
    const double lam = (double)th[1];
    const double K   = (double)th[7];
    const double Dp  = D * L_RATIO;

    // register state
    uint32_t pk[RPT][3];             // packed byte offsets (idx*4), pad slot 4096*4
    float wf[RPT], bhf[RPT];
    float rg[RPT], dxg[RPT], vr[RPT], ug[RPT], pw[RPT];

    // ---- setup: dedupe neighbours, Jacobi weights, hatted RHS ----
    double bb_part = 0.0;
#pragma unroll
    for (int t = 0; t < RPT; t++) {
        const int i = tid + t * NT;
        int nb[6];
#pragma unroll
        for (int j = 0; j < 6; j++) nb[j] = nbr[i * 6 + j];
#pragma unroll
        for (int j = 1; j < 6; j++)
#pragma unroll
            for (int l = 0; l < 6; l++)
                if (l < j && nb[j] == nb[l]) nb[j] = NROW;
        pk[t][0] = ((uint32_t)nb[0] * 4u) | (((uint32_t)nb[1] * 4u) << 16);
        pk[t][1] = ((uint32_t)nb[2] * 4u) | (((uint32_t)nb[3] * 4u) << 16);
        pk[t][2] = ((uint32_t)nb[4] * 4u) | (((uint32_t)nb[5] * 4u) << 16);

        double drec = 0.0, drho = 0.0;
#pragma unroll
        for (int c = 0; c < NCELL; c++) {
            const double f = (double)cd[i * NCELL + c];
            drec += f * ((double)th[8 + c] * K);
            drho += f * (double)th[2 + c];
        }
        const double diag = 6.0 * Dp + AREA * (lam + drec);
        wf[t] = (float)(Dp / diag);
        const double bh = AREA * drho * B_SCALE / (A_SCALE * diag);
        bhf[t] = (float)bh;
        pw[t]  = 1.0f;               // power-iteration start: e
        dxg[t] = 0.0f;
        bb_part += bh * bh;
    }
    if (tid == 0) { rfA[NROW] = 0.0f; rfB[NROW] = 0.0f; xd[NROW] = 0.0; }
    __syncthreads();

    const double bb   = blk_red_d(bb_part, scrd, tid);
    const double tolo = bb * 1e-13;          // outer relres ~3e-7

    // ---- power iteration: v = N^POWK e  (1 barrier/step, no reductions) ----
#pragma unroll 1
    for (int k = 0; k < POWK; k++) {
        float* buf = (k & 1) ? rfB : rfA;
#pragma unroll
        for (int t = 0; t < RPT; t++) buf[tid + t * NT] = pw[t];
        __syncthreads();
#pragma unroll
        for (int t = 0; t < RPT; t++)
            pw[t] = wf[t] * GATHF(buf, pk[t][0], pk[t][1], pk[t][2]);
    }
#pragma unroll
    for (int t = 0; t < RPT; t++) vr[t] = pw[t];

    // ---- u = (I - N) v in fp64 (cancellation-critical step) ----
#pragma unroll
    for (int t = 0; t < RPT; t++) xd[tid + t * NT] = (double)vr[t];
    __syncthreads();
    {
        double uu_p = 0.0;
#pragma unroll
        for (int t = 0; t < RPT; t++) {
            const int i = tid + t * NT;
            const double sum = GATHD(xd, pk[t][0], pk[t][1], pk[t][2]);
            double drec = 0.0;
#pragma unroll
            for (int c = 0; c < NCELL; c++)
                drec += (double)cd[i * NCELL + c] * ((double)th[8 + c] * K);
            const double diag = 6.0 * Dp + AREA * (lam + drec);
            const double ud = (double)vr[t] - (Dp / diag) * sum;
            ug[t] = (float)ud;
            uu_p += ud * ud;
        }
        const double uu = blk_red_d(uu_p, scrd, tid);   // barriers also end xd reads
        scrf[30] = (uu > 0.0) ? (float)(1.0 / uu) : 0.0f;  // broadcast 1/uu
    }
#pragma unroll
    for (int t = 0; t < RPT; t++) { xd[tid + t * NT] = 0.0; rg[t] = bhf[t]; }
    // (xd zeroing: each thread owns its slots; visibility ordered by fold barrier)

    double rn2d = bb;

#pragma unroll 1
    for (int outer = 0; outer < MAX_OUTER && rn2d > tolo; outer++) {
        // -- 1D Galerkin deflation of the Perron outlier: c = <u,r>/<u,u> --
        float cp = 0.0f;
#pragma unroll
        for (int t = 0; t < RPT; t++) cp = fmaf(ug[t], rg[t], cp);
        cp = bred1(cp, scrf, tid);
        const float c = cp * scrf[30];
#pragma unroll
        for (int t = 0; t < RPT; t++) {
            dxg[t] = fmaf(c, vr[t], dxg[t]);
            rg[t]  = fmaf(-c, ug[t], rg[t]);
        }

        // -- NEUM Richardson/Neumann steps: x += r ; r = N r --
#pragma unroll 1
        for (int k = 0; k < NEUM; k++) {
            float* buf = (k & 1) ? rfB : rfA;
#pragma unroll
            for (int t = 0; t < RPT; t++) buf[tid + t * NT] = rg[t];
            __syncthreads();
#pragma unroll
            for (int t = 0; t < RPT; t++) {
                const float sum = GATHF(buf, pk[t][0], pk[t][1], pk[t][2]);
                dxg[t] += rg[t];
                rg[t] = wf[t] * sum;
            }
        }

        // -- fold dx into fp64 x ; true fp64 residual ; restart --
#pragma unroll
        for (int t = 0; t < RPT; t++) {
            xd[tid + t * NT] += (double)dxg[t];
            dxg[t] = 0.0f;
        }
        __syncthreads();
        double rp = 0.0;
#pragma unroll
        for (int t = 0; t < RPT; t++) {
            const int i = tid + t * NT;
            const double sum = GATHD(xd, pk[t][0], pk[t][1], pk[t][2]);
            double drec = 0.0, drho = 0.0;
#pragma unroll
            for (int cc = 0; cc < NCELL; cc++) {
                const double f = (double)cd[i * NCELL + cc];
                drec += f * ((double)th[8 + cc] * K);
                drho += f * (double)th[2 + cc];
            }
            const double diag = 6.0 * Dp + AREA * (lam + drec);
            const double bh   = AREA * drho * B_SCALE / (A_SCALE * diag);
            const double rdi  = bh - (xd[i] - (Dp / diag) * sum);
            rg[t] = (float)rdi;
            rp += rdi * rdi;
        }
        rn2d = blk_red_d(rp, scrd, tid);
    }

    // ---- epilogue (fp64) ----
    double part[NCELL] = {0, 0, 0, 0, 0};
    double rho_p[NCELL], rec[NCELL];
#pragma unroll
    for (int c = 0; c < NCELL; c++) {
        rho_p[c] = (double)th[2 + c];
        rec[c]   = (double)th[8 + c];
    }
#pragma unroll
    for (int t = 0; t < RPT; t++) {
        const int i = tid + t * NT;
        double num[NCELL], den = 0.0;
#pragma unroll
        for (int c = 0; c < NCELL; c++) {
            num[c] = (double)cd[i * NCELL + c] * rho_p[c];
            den += num[c];
        }
        const double gi = xd[i] / den;
#pragma unroll
        for (int c = 0; c < NCELL; c++) part[c] += gi * num[c];
    }
    bredd5(part, scrd, tid);

    if (tid < 25) {
        const int a = tid / 5, c = tid % 5;
        g_IM[sys * 25 + tid] = K * rec[a] * part[c] / (double)NROW;
        __threadfence();
    }
    __syncthreads();

    // ---- last block computes the loss ----
    if (tid == 0) {
        __threadfence();
        s_last = (atomicAdd(&g_cnt, 1) == 2) ? 1 : 0;
    }
    __syncthreads();
    if (s_last && tid < 32) {
        __threadfence();
        double s_m = 0, s_d = 0, s_mm = 0, s_dd = 0, s_md = 0;
        for (int i = tid; i < 75; i += 32) {
            const double m = *((volatile double*)&g_IM[i]);
            const double d = (double)Iexp[i];
            s_m += m; s_d += d; s_mm += m * m; s_dd += d * d; s_md += m * d;
        }
        s_m  = warp_red_d(s_m);
        s_d  = warp_red_d(s_d);
        s_mm = warp_red_d(s_mm);
        s_dd = warp_red_d(s_dd);
        s_md = warp_red_d(s_md);
        if (tid == 0) {
            const double n  = 75.0;
            const double mm = s_m / n, md = s_d / n;
            const double cov = s_md / n - mm * md;
            const double vm  = s_mm / n - mm * mm;
            const double vd  = s_dd / n - md * md;
            out[0] = (float)(1.0 - cov / (sqrt(vm) * sqrt(vd)));
            atomicExch(&g_cnt, 0);
        }
    }
}

extern "C" void kernel_launch(void* const* d_in, const int* in_sizes, int n_in,
                              void* d_out, int out_size)
{
    const float* th1  = (const float*)d_in[0];
    const float* th2  = (const float*)d_in[1];
    const float* th3  = (const float*)d_in[2];
    const float* cd   = (const float*)d_in[3];
    const float* Iexp = (const float*)d_in[4];
    const int*   nbr  = (const int*)d_in[5];

    cudaFuncSetAttribute(solve_kernel,
                         cudaFuncAttributeMaxDynamicSharedMemorySize, SM_BYTES);

    solve_kernel<<<3, NT, SM_BYTES>>>(th1, th2, th3, cd, Iexp, nbr, (float*)d_out);
}

// round 8
// speedup vs baseline: 1.2702x; 1.2702x over previous
#include <cuda_runtime.h>
#include <math.h>
#include <stdint.h>

#define NROW      4096
#define NT        512
#define RPT       8
#define NCELL     5
#define MAXIT_IN  14
#define MAX_OUTER 3

// smem doubles: xd[4097] wdm[4096] bhdm[4096] scrd[40]; floats: pf[4097] sf[4097] scrf[96]
#define SM_BYTES ((4097 + 4096 + 4096 + 40) * 8 + (4097 + 4097 + 96) * 4)

__device__ double g_IM[75];
__device__ int    g_cnt = 0;

__device__ __forceinline__ double warp_red_d(double v) {
#pragma unroll
    for (int o = 16; o; o >>= 1) v += __shfl_down_sync(0xFFFFFFFFu, v, o);
    return v;
}
__device__ __forceinline__ double blk_red_d(double v, double* scr, int tid) {
    int lane = tid & 31, wid = tid >> 5;
    v = warp_red_d(v);
    if (lane == 0) scr[wid] = v;
    __syncthreads();
    if (wid == 0) {
        double u = (lane < 16) ? scr[lane] : 0.0;
#pragma unroll
        for (int o = 8; o; o >>= 1) u += __shfl_down_sync(0xFFFFFFFFu, u, o);
        if (lane == 0) scr[32] = u;
    }
    __syncthreads();
    return scr[32];
}
__device__ __forceinline__ void bredd5(double v[5], double* scr, int tid) {
    int lane = tid & 31, wid = tid >> 5;
#pragma unroll
    for (int k = 0; k < 5; k++) v[k] = warp_red_d(v[k]);
    if (lane == 0) {
#pragma unroll
        for (int k = 0; k < 5; k++) scr[k * 16 + wid] = v[k];
    }
    __syncthreads();
    if (wid < 5) {
        double u = (lane < 16) ? scr[wid * 16 + lane] : 0.0;
#pragma unroll
        for (int o = 8; o; o >>= 1) u += __shfl_down_sync(0xFFFFFFFFu, u, o);
        if (lane == 0) scr[80 + wid] = u;
    }
    __syncthreads();
#pragma unroll
    for (int k = 0; k < 5; k++) v[k] = scr[80 + k];
}
// single-barrier fp32 reductions (16 warps); disjoint scr regions per call site
__device__ __forceinline__ float bred1(float v, float* scr, int tid) {
    const int lane = tid & 31, wid = tid >> 5;
#pragma unroll
    for (int o = 16; o; o >>= 1) v += __shfl_xor_sync(0xFFFFFFFFu, v, o);
    if (lane == 0) scr[wid] = v;
    __syncthreads();
    float u = scr[lane & 15];
#pragma unroll
    for (int o = 8; o; o >>= 1) u += __shfl_xor_sync(0xFFFFFFFFu, u, o);
    return u;
}
__device__ __forceinline__ void bred2(float& a, float& b, float* scr, int tid) {
    const int lane = tid & 31, wid = tid >> 5;
#pragma unroll
    for (int o = 16; o; o >>= 1) {
        a += __shfl_xor_sync(0xFFFFFFFFu, a, o);
        b += __shfl_xor_sync(0xFFFFFFFFu, b, o);
    }
    if (lane == 0) { scr[wid] = a; scr[16 + wid] = b; }
    __syncthreads();
    float ua = scr[lane & 15];
    float ub = scr[16 + (lane & 15)];
#pragma unroll
    for (int o = 8; o; o >>= 1) {
        ua += __shfl_xor_sync(0xFFFFFFFFu, ua, o);
        ub += __shfl_xor_sync(0xFFFFFFFFu, ub, o);
    }
    a = ua; b = ub;
}

#define GATHF(arr, q0, q1, q2)                                                \
    ( *(const float*)((const char*)(arr) + ((q0) & 0xFFFFu))                  \
    + *(const float*)((const char*)(arr) + ((q0) >> 16))                      \
    + *(const float*)((const char*)(arr) + ((q1) & 0xFFFFu))                  \
    + *(const float*)((const char*)(arr) + ((q1) >> 16))                      \
    + *(const float*)((const char*)(arr) + ((q2) & 0xFFFFu))                  \
    + *(const float*)((const char*)(arr) + ((q2) >> 16)) )
#define GATHD(arr, q0, q1, q2)                                                \
    ( *(const double*)((const char*)(arr) + (((q0) & 0xFFFFu) << 1))          \
    + *(const double*)((const char*)(arr) + (((q0) >> 16)     << 1))          \
    + *(const double*)((const char*)(arr) + (((q1) & 0xFFFFu) << 1))          \
    + *(const double*)((const char*)(arr) + (((q1) >> 16)     << 1))          \
    + *(const double*)((const char*)(arr) + (((q2) & 0xFFFFu) << 1))          \
    + *(const double*)((const char*)(arr) + (((q2) >> 16)     << 1)) )

__global__ __launch_bounds__(NT, 1)
void solve_kernel(const float* __restrict__ th1,
                  const float* __restrict__ th2,
                  const float* __restrict__ th3,
                  const float* __restrict__ cd,
                  const float* __restrict__ Iexp,
                  const int*   __restrict__ nbr,
                  float*       __restrict__ out)
{
    extern __shared__ double sm[];
    double* xd   = sm;                 // 4097 (pad slot 4096 == 0)
    double* wdm  = sm + 4097;          // 4096 : fp64 Jacobi weight
    double* bhdm = sm + 8193;          // 4096 : fp64 hatted RHS
    double* scrd = sm + 12289;         // 40
    float*  fb   = (float*)(sm + 12329);
    float* pf   = fb;                  // 4097 (pad 0)
    float* sf   = fb + 4097;           // 4097 (pad 0)
    float* scrf = fb + 8194;           // 96 : [0..15] bred1, [16..47] bred2a, [48..79] bred2b
    __shared__ int s_last;

    const int tid = threadIdx.x;
    const int sys = blockIdx.x;
    const float* th = (sys == 0) ? th1 : ((sys == 1) ? th2 : th3);

    const double L_C     = 8.45e-05;
    const double L_RATIO = 1.0 / sqrt(3.0);
    const double AREA    = sqrt(3.0) * 0.5 * L_C * L_C;
    const double A_SCALE = 1.0e11;
    const double B_SCALE = 1.0e23;

    const double D   = (double)th[0];
    const double lam = (double)th[1];
    const double K   = (double)th[7];
    double rho_p[NCELL], rec[NCELL], recK[NCELL];
#pragma unroll
    for (int c = 0; c < NCELL; c++) {
        rho_p[c] = (double)th[2 + c];
        rec[c]   = (double)th[8 + c];
        recK[c]  = rec[c] * K;
    }
    const double Dp = D * L_RATIO;

    // per-thread register state (fp32 hot loop)
    uint32_t pk[RPT][3];               // packed byte offsets (idx*4), pad = 4096*4
    float wf[RPT], r0g[RPT];
    float rg[RPT], pg[RPT], vg[RPT], sg[RPT], tg[RPT], dx[RPT];

    // ---- setup ----
    double bb_part = 0.0;
#pragma unroll
    for (int t = 0; t < RPT; t++) {
        const int i = tid + t * NT;
        int nb[6];
#pragma unroll
        for (int j = 0; j < 6; j++) nb[j] = nbr[i * 6 + j];
#pragma unroll
        for (int j = 1; j < 6; j++)
#pragma unroll
            for (int l = 0; l < 6; l++)
                if (l < j && nb[j] == nb[l]) nb[j] = NROW;   // dup -> pad slot
        pk[t][0] = ((uint32_t)nb[0] * 4u) | (((uint32_t)nb[1] * 4u) << 16);
        pk[t][1] = ((uint32_t)nb[2] * 4u) | (((uint32_t)nb[3] * 4u) << 16);
        pk[t][2] = ((uint32_t)nb[4] * 4u) | (((uint32_t)nb[5] * 4u) << 16);

        double drec = 0.0, drho = 0.0;
#pragma unroll
        for (int c = 0; c < NCELL; c++) {
            const double f = (double)cd[i * NCELL + c];
            drec += f * recK[c];
            drho += f * rho_p[c];
        }
        const double diag = 6.0 * Dp + AREA * (lam + drec);
        const double wdv  = Dp / diag;
        const double bh   = AREA * drho * B_SCALE / (A_SCALE * diag);
        wdm[i]  = wdv;
        bhdm[i] = bh;
        wf[t]   = (float)wdv;
        const float bhf = (float)bh;
        r0g[t] = bhf; rg[t] = bhf;
        pg[t] = 0.0f; vg[t] = 0.0f; dx[t] = 0.0f;
        xd[i] = 0.0;
        bb_part += bh * bh;
    }
    if (tid == 0) { pf[NROW] = 0.0f; sf[NROW] = 0.0f; xd[NROW] = 0.0; }
    __syncthreads();

    const double bb   = blk_red_d(bb_part, scrd, tid);
    const double tolo = bb * 1e-12;    // outer relres 1e-6
    double rn2d = bb;

#pragma unroll 1
    for (int outer = 0; outer < MAX_OUTER && rn2d > tolo; outer++) {
        const float tol2 = (float)fmax(rn2d * 1e-6, tolo);   // inner relres 1e-3
        float rho = (float)rn2d, rn2 = rho;
        float rho_o = 1.0f, alpha = 1.0f, omega = 1.0f;
        float best = rn2; int since = 0;

#pragma unroll 1
        for (int it = 0; it < MAXIT_IN; it++) {
            const float beta = (it == 0) ? 0.0f
                             : __fdividef(rho * alpha, rho_o * omega);

            // p = r + beta*(p - omega*v) ; publish
#pragma unroll
            for (int t = 0; t < RPT; t++) {
                pg[t] = fmaf(beta, fmaf(-omega, vg[t], pg[t]), rg[t]);
                pf[tid + t * NT] = pg[t];
            }
            __syncthreads();

            // v = A_hat p ; c0 = <r0,v>
            float c0 = 0.0f;
#pragma unroll
            for (int t = 0; t < RPT; t++) {
                const float sum = GATHF(pf, pk[t][0], pk[t][1], pk[t][2]);
                vg[t] = fmaf(-wf[t], sum, pg[t]);
                c0 = fmaf(r0g[t], vg[t], c0);
            }
            c0 = bred1(c0, scrf, tid);
            if (fabsf(c0) < 1e-33f) break;
            alpha = __fdividef(rho, c0);

            // s = r - alpha*v ; publish
#pragma unroll
            for (int t = 0; t < RPT; t++) {
                sg[t] = fmaf(-alpha, vg[t], rg[t]);
                sf[tid + t * NT] = sg[t];
            }
            __syncthreads();

            // t = A_hat s ; st=<t,s>, tt=<t,t>
            float st = 0.0f, tt = 0.0f;
#pragma unroll
            for (int t = 0; t < RPT; t++) {
                const float sum = GATHF(sf, pk[t][0], pk[t][1], pk[t][2]);
                tg[t] = fmaf(-wf[t], sum, sg[t]);
                st = fmaf(tg[t], sg[t], st);
                tt = fmaf(tg[t], tg[t], tt);
            }
            bred2(st, tt, scrf + 16, tid);
            if (!(tt > 0.0f)) {
#pragma unroll
                for (int t = 0; t < RPT; t++) dx[t] = fmaf(alpha, pg[t], dx[t]);
                break;
            }
            omega = __fdividef(st, tt);

            // dx += alpha p + omega s ; r = s - omega t ; exact new dots
            float r0r = 0.0f, rr = 0.0f;
#pragma unroll
            for (int t = 0; t < RPT; t++) {
                dx[t] = fmaf(alpha, pg[t], fmaf(omega, sg[t], dx[t]));
                rg[t] = fmaf(-omega, tg[t], sg[t]);
                r0r = fmaf(r0g[t], rg[t], r0r);
                rr  = fmaf(rg[t],  rg[t], rr);
            }
            bred2(r0r, rr, scrf + 48, tid);
            rho_o = rho; rho = r0r; rn2 = rr;
            if (rn2 <= tol2) break;
            if (rn2 < best) { best = rn2; since = 0; }
            else if (++since >= 3) break;
            if (fabsf(rho) < 1e-33f) break;
        }

        // ---- fold dx into fp64 x ; true fp64 residual (smem-cached w, bh) ----
#pragma unroll
        for (int t = 0; t < RPT; t++) {
            xd[tid + t * NT] += (double)dx[t];
            dx[t] = 0.0f;
        }
        __syncthreads();
        double rp = 0.0;
#pragma unroll
        for (int t = 0; t < RPT; t++) {
            const int i = tid + t * NT;
            const double sum = GATHD(xd, pk[t][0], pk[t][1], pk[t][2]);
            const double rdi = bhdm[i] - (xd[i] - wdm[i] * sum);
            const float rdf = (float)rdi;
            r0g[t] = rdf; rg[t] = rdf;
            pg[t] = 0.0f; vg[t] = 0.0f;
            rp += rdi * rdi;
        }
        rn2d = blk_red_d(rp, scrd, tid);   // also orders state for next pass
    }

    // ---- epilogue (fp64) ----
    double part[NCELL] = {0, 0, 0, 0, 0};
#pragma unroll
    for (int t = 0; t < RPT; t++) {
        const int i = tid + t * NT;
        double num[NCELL], den = 0.0;
#pragma unroll
        for (int c = 0; c < NCELL; c++) {
            num[c] = (double)cd[i * NCELL + c] * rho_p[c];
            den += num[c];
        }
        const double gi = xd[i] / den;
#pragma unroll
        for (int c = 0; c < NCELL; c++) part[c] += gi * num[c];
    }
    bredd5(part, scrd, tid);

    if (tid < 25) {
        const int a = tid / 5, c = tid % 5;
        g_IM[sys * 25 + tid] = K * rec[a] * part[c] / (double)NROW;
        __threadfence();
    }
    __syncthreads();

    // ---- last block computes the loss ----
    if (tid == 0) {
        __threadfence();
        s_last = (atomicAdd(&g_cnt, 1) == 2) ? 1 : 0;
    }
    __syncthreads();
    if (s_last && tid < 32) {
        __threadfence();
        double s_m = 0, s_d = 0, s_mm = 0, s_dd = 0, s_md = 0;
        for (int i = tid; i < 75; i += 32) {
            const double m = *((volatile double*)&g_IM[i]);
            const double d = (double)Iexp[i];
            s_m += m; s_d += d; s_mm += m * m; s_dd += d * d; s_md += m * d;
        }
        s_m  = warp_red_d(s_m);
        s_d  = warp_red_d(s_d);
        s_mm = warp_red_d(s_mm);
        s_dd = warp_red_d(s_dd);
        s_md = warp_red_d(s_md);
        if (tid == 0) {
            const double n  = 75.0;
            const double mm = s_m / n, md = s_d / n;
            const double cov = s_md / n - mm * md;
            const double vm  = s_mm / n - mm * mm;
            const double vd  = s_dd / n - md * md;
            out[0] = (float)(1.0 - cov / (sqrt(vm) * sqrt(vd)));
            atomicExch(&g_cnt, 0);
        }
    }
}

extern "C" void kernel_launch(void* const* d_in, const int* in_sizes, int n_in,
                              void* d_out, int out_size)
{
    const float* th1  = (const float*)d_in[0];
    const float* th2  = (const float*)d_in[1];
    const float* th3  = (const float*)d_in[2];
    const float* cd   = (const float*)d_in[3];
    const float* Iexp = (const float*)d_in[4];
    const int*   nbr  = (const int*)d_in[5];

    cudaFuncSetAttribute(solve_kernel,
                         cudaFuncAttributeMaxDynamicSharedMemorySize, SM_BYTES);

    solve_kernel<<<3, NT, SM_BYTES>>>(th1, th2, th3, cd, Iexp, nbr, (float*)d_out);
}

// round 9
// speedup vs baseline: 1.4177x; 1.1162x over previous
#include <cuda_runtime.h>
#include <math.h>
#include <stdint.h>

#define NROW      4096
#define NT        512
#define RPT       8
#define NCELL     5
#define POWK      12     // power-iteration steps for Perron eigenvector
#define NEUM1     12     // Richardson steps, first pass
#define NEUM2     8      // Richardson steps, later passes
#define MAX_OUTER 5

// smem doubles: xd[4097] wdm[4096] bhdm[4096] scrd[40]; floats: pf[4097] sf[4097] scrf[32]
#define SM_BYTES ((4097 + 4096 + 4096 + 40) * 8 + (4097 + 4097 + 32) * 4)

__device__ double g_IM[75];
__device__ int    g_cnt = 0;

__device__ __forceinline__ double warp_red_d(double v) {
#pragma unroll
    for (int o = 16; o; o >>= 1) v += __shfl_down_sync(0xFFFFFFFFu, v, o);
    return v;
}
__device__ __forceinline__ double blk_red_d(double v, double* scr, int tid) {
    int lane = tid & 31, wid = tid >> 5;
    v = warp_red_d(v);
    if (lane == 0) scr[wid] = v;
    __syncthreads();
    if (wid == 0) {
        double u = (lane < 16) ? scr[lane] : 0.0;
#pragma unroll
        for (int o = 8; o; o >>= 1) u += __shfl_down_sync(0xFFFFFFFFu, u, o);
        if (lane == 0) scr[32] = u;
    }
    __syncthreads();
    return scr[32];
}
__device__ __forceinline__ void bredd5(double v[5], double* scr, int tid) {
    int lane = tid & 31, wid = tid >> 5;
#pragma unroll
    for (int k = 0; k < 5; k++) v[k] = warp_red_d(v[k]);
    if (lane == 0) {
#pragma unroll
        for (int k = 0; k < 5; k++) scr[k * 16 + wid] = v[k];
    }
    __syncthreads();
    if (wid < 5) {
        double u = (lane < 16) ? scr[wid * 16 + lane] : 0.0;
#pragma unroll
        for (int o = 8; o; o >>= 1) u += __shfl_down_sync(0xFFFFFFFFu, u, o);
        if (lane == 0) scr[80 + wid] = u;
    }
    __syncthreads();
#pragma unroll
    for (int k = 0; k < 5; k++) v[k] = scr[80 + k];
}
// single-barrier fp32 block reduction (16 warps)
__device__ __forceinline__ float bred1(float v, float* scr, int tid) {
    const int lane = tid & 31, wid = tid >> 5;
#pragma unroll
    for (int o = 16; o; o >>= 1) v += __shfl_xor_sync(0xFFFFFFFFu, v, o);
    if (lane == 0) scr[wid] = v;
    __syncthreads();
    float u = scr[lane & 15];
#pragma unroll
    for (int o = 8; o; o >>= 1) u += __shfl_xor_sync(0xFFFFFFFFu, u, o);
    return u;
}

#define GATHF(arr, q0, q1, q2)                                                \
    ( *(const float*)((const char*)(arr) + ((q0) & 0xFFFFu))                  \
    + *(const float*)((const char*)(arr) + ((q0) >> 16))                      \
    + *(const float*)((const char*)(arr) + ((q1) & 0xFFFFu))                  \
    + *(const float*)((const char*)(arr) + ((q1) >> 16))                      \
    + *(const float*)((const char*)(arr) + ((q2) & 0xFFFFu))                  \
    + *(const float*)((const char*)(arr) + ((q2) >> 16)) )
#define GATHD(arr, q0, q1, q2)                                                \
    ( *(const double*)((const char*)(arr) + (((q0) & 0xFFFFu) << 1))          \
    + *(const double*)((const char*)(arr) + (((q0) >> 16)     << 1))          \
    + *(const double*)((const char*)(arr) + (((q1) & 0xFFFFu) << 1))          \
    + *(const double*)((const char*)(arr) + (((q1) >> 16)     << 1))          \
    + *(const double*)((const char*)(arr) + (((q2) & 0xFFFFu) << 1))          \
    + *(const double*)((const char*)(arr) + (((q2) >> 16)     << 1)) )

__global__ __launch_bounds__(NT, 1)
void solve_kernel(const float* __restrict__ th1,
                  const float* __restrict__ th2,
                  const float* __restrict__ th3,
                  const float* __restrict__ cd,
                  const float* __restrict__ Iexp,
                  const int*   __restrict__ nbr,
                  float*       __restrict__ out)
{
    extern __shared__ double sm[];
    double* xd   = sm;                 // 4097 (pad slot 4096 == 0)
    double* wdm  = sm + 4097;          // 4096 fp64 Jacobi weight
    double* bhdm = sm + 8193;          // 4096 fp64 hatted RHS
    double* scrd = sm + 12289;         // 40
    float*  fb   = (float*)(sm + 12329);
    float* pf   = fb;                  // 4097 (pad 0) — buffer A
    float* sf   = fb + 4097;           // 4097 (pad 0) — buffer B
    float* scrf = fb + 8194;           // 32
    __shared__ int s_last;

    const int tid = threadIdx.x;
    const int sys = blockIdx.x;
    const float* th = (sys == 0) ? th1 : ((sys == 1) ? th2 : th3);

    const double L_C     = 8.45e-05;
    const double L_RATIO = 1.0 / sqrt(3.0);
    const double AREA    = sqrt(3.0) * 0.5 * L_C * L_C;
    const double A_SCALE = 1.0e11;
    const double B_SCALE = 1.0e23;

    const double D   = (double)th[0];
    const double lam = (double)th[1];
    const double K   = (double)th[7];
    double rho_p[NCELL], rec[NCELL], recK[NCELL];
#pragma unroll
    for (int c = 0; c < NCELL; c++) {
        rho_p[c] = (double)th[2 + c];
        rec[c]   = (double)th[8 + c];
        recK[c]  = rec[c] * K;
    }
    const double Dp = D * L_RATIO;

    // register state
    uint32_t pk[RPT][3];               // packed byte offsets (idx*4), pad = 4096*4
    float wf[RPT];
    float rg[RPT], dx[RPT], vr[RPT], ug[RPT];

    // ---- setup ----
    double bb_part = 0.0;
#pragma unroll
    for (int t = 0; t < RPT; t++) {
        const int i = tid + t * NT;
        int nb[6];
#pragma unroll
        for (int j = 0; j < 6; j++) nb[j] = nbr[i * 6 + j];
#pragma unroll
        for (int j = 1; j < 6; j++)
#pragma unroll
            for (int l = 0; l < 6; l++)
                if (l < j && nb[j] == nb[l]) nb[j] = NROW;   // dup -> pad slot
        pk[t][0] = ((uint32_t)nb[0] * 4u) | (((uint32_t)nb[1] * 4u) << 16);
        pk[t][1] = ((uint32_t)nb[2] * 4u) | (((uint32_t)nb[3] * 4u) << 16);
        pk[t][2] = ((uint32_t)nb[4] * 4u) | (((uint32_t)nb[5] * 4u) << 16);

        double drec = 0.0, drho = 0.0;
#pragma unroll
        for (int c = 0; c < NCELL; c++) {
            const double f = (double)cd[i * NCELL + c];
            drec += f * recK[c];
            drho += f * rho_p[c];
        }
        const double diag = 6.0 * Dp + AREA * (lam + drec);
        const double wdv  = Dp / diag;
        const double bh   = AREA * drho * B_SCALE / (A_SCALE * diag);
        wdm[i]  = wdv;
        bhdm[i] = bh;
        wf[t]   = (float)wdv;
        rg[t]   = (float)bh;
        dx[t]   = 0.0f;
        vr[t]   = 1.0f;                 // power iteration start: e
        xd[i]   = 0.0;
        bb_part += bh * bh;
    }
    if (tid == 0) { pf[NROW] = 0.0f; sf[NROW] = 0.0f; xd[NROW] = 0.0; }
    __syncthreads();

    const double bb   = blk_red_d(bb_part, scrd, tid);
    const double tolo = bb * 1e-10;    // outer relres 1e-5

    // ---- power iteration: v = N^POWK e (1 barrier/step) ----
#pragma unroll 1
    for (int k = 0; k < POWK; k++) {
        float* buf = (k & 1) ? sf : pf;
#pragma unroll
        for (int t = 0; t < RPT; t++) buf[tid + t * NT] = vr[t];
        __syncthreads();
#pragma unroll
        for (int t = 0; t < RPT; t++)
            vr[t] = wf[t] * GATHF(buf, pk[t][0], pk[t][1], pk[t][2]);
    }

    // ---- u = (I - N) v in fp64 (cancellation-critical) ----
#pragma unroll
    for (int t = 0; t < RPT; t++) xd[tid + t * NT] = (double)vr[t];
    __syncthreads();
    float inv_uu;
    {
        double uu_p = 0.0;
#pragma unroll
        for (int t = 0; t < RPT; t++) {
            const int i = tid + t * NT;
            const double sum = GATHD(xd, pk[t][0], pk[t][1], pk[t][2]);
            const double ud  = (double)vr[t] - wdm[i] * sum;
            ug[t] = (float)ud;
            uu_p += ud * ud;
        }
        const double uu = blk_red_d(uu_p, scrd, tid);   // barriers end xd reads
        inv_uu = (uu > 0.0) ? (float)(1.0 / uu) : 0.0f;
    }
#pragma unroll
    for (int t = 0; t < RPT; t++) xd[tid + t * NT] = 0.0;   // own slots only

    double rn2d = bb;

#pragma unroll 1
    for (int outer = 0; outer < MAX_OUTER && rn2d > tolo; outer++) {
        // -- deflate Perron mode: c = <u,r>/<u,u> ; fp64 C folded at pass end --
        float up = 0.0f;
#pragma unroll
        for (int t = 0; t < RPT; t++) up = fmaf(ug[t], rg[t], up);
        up = bred1(up, scrf, tid);
        const float  c  = up * inv_uu;
        const double Cd = (double)c;
#pragma unroll
        for (int t = 0; t < RPT; t++) rg[t] = fmaf(-c, ug[t], rg[t]);

        // -- Richardson: dx += r ; r = N r  (1 barrier/step) --
        const int nsteps = (outer == 0) ? NEUM1 : NEUM2;
#pragma unroll 1
        for (int k = 0; k < nsteps; k++) {
            float* buf = (k & 1) ? sf : pf;
#pragma unroll
            for (int t = 0; t < RPT; t++) buf[tid + t * NT] = rg[t];
            __syncthreads();
#pragma unroll
            for (int t = 0; t < RPT; t++) {
                const float sum = GATHF(buf, pk[t][0], pk[t][1], pk[t][2]);
                dx[t] += rg[t];
                rg[t] = wf[t] * sum;
            }
        }

        // -- fold (fp64: bulk dx + deflation C·v) ; true fp64 residual --
#pragma unroll
        for (int t = 0; t < RPT; t++) {
            xd[tid + t * NT] += (double)dx[t] + Cd * (double)vr[t];
            dx[t] = 0.0f;
        }
        __syncthreads();
        double rp = 0.0;
#pragma unroll
        for (int t = 0; t < RPT; t++) {
            const int i = tid + t * NT;
            const double sum = GATHD(xd, pk[t][0], pk[t][1], pk[t][2]);
            const double rdi = bhdm[i] - (xd[i] - wdm[i] * sum);
            rg[t] = (float)rdi;
            rp += rdi * rdi;
        }
        rn2d = blk_red_d(rp, scrd, tid);   // also orders state for next pass
    }

    // ---- epilogue (fp64) ----
    double part[NCELL] = {0, 0, 0, 0, 0};
#pragma unroll
    for (int t = 0; t < RPT; t++) {
        const int i = tid + t * NT;
        double num[NCELL], den = 0.0;
#pragma unroll
        for (int c = 0; c < NCELL; c++) {
            num[c] = (double)cd[i * NCELL + c] * rho_p[c];
            den += num[c];
        }
        const double gi = xd[i] / den;
#pragma unroll
        for (int c = 0; c < NCELL; c++) part[c] += gi * num[c];
    }
    bredd5(part, scrd, tid);

    if (tid < 25) {
        const int a = tid / 5, c = tid % 5;
        g_IM[sys * 25 + tid] = K * rec[a] * part[c] / (double)NROW;
        __threadfence();
    }
    __syncthreads();

    // ---- last block computes the loss ----
    if (tid == 0) {
        __threadfence();
        s_last = (atomicAdd(&g_cnt, 1) == 2) ? 1 : 0;
    }
    __syncthreads();
    if (s_last && tid < 32) {
        __threadfence();
        double s_m = 0, s_d = 0, s_mm = 0, s_dd = 0, s_md = 0;
        for (int i = tid; i < 75; i += 32) {
            const double m = *((volatile double*)&g_IM[i]);
            const double d = (double)Iexp[i];
            s_m += m; s_d += d; s_mm += m * m; s_dd += d * d; s_md += m * d;
        }
        s_m  = warp_red_d(s_m);
        s_d  = warp_red_d(s_d);
        s_mm = warp_red_d(s_mm);
        s_dd = warp_red_d(s_dd);
        s_md = warp_red_d(s_md);
        if (tid == 0) {
            const double n  = 75.0;
            const double mm = s_m / n, md = s_d / n;
            const double cov = s_md / n - mm * md;
            const double vm  = s_mm / n - mm * mm;
            const double vd  = s_dd / n - md * md;
            out[0] = (float)(1.0 - cov / (sqrt(vm) * sqrt(vd)));
            atomicExch(&g_cnt, 0);
        }
    }
}

extern "C" void kernel_launch(void* const* d_in, const int* in_sizes, int n_in,
                              void* d_out, int out_size)
{
    const float* th1  = (const float*)d_in[0];
    const float* th2  = (const float*)d_in[1];
    const float* th3  = (const float*)d_in[2];
    const float* cd   = (const float*)d_in[3];
    const float* Iexp = (const float*)d_in[4];
    const int*   nbr  = (const int*)d_in[5];

    cudaFuncSetAttribute(solve_kernel,
                         cudaFuncAttributeMaxDynamicSharedMemorySize, SM_BYTES);

    solve_kernel<<<3, NT, SM_BYTES>>>(th1, th2, th3, cd, Iexp, nbr, (float*)d_out);
}